// round 15
// baseline (speedup 1.0000x reference)
#include <cuda_runtime.h>
#include <cuda.h>
#include <cstdint>

// ============================================================
// QuantizedConv2d exact int conv via split-weight int8 mma.sync GEMM
//   x[8,128,56,56], w[256,128,3,3], bias[256], shift=16 (structural)
//   out[8,256,56,56] = (conv(x,w)+bias) >> 16
// w = (w>>8)*256 + (w&255): hi s8 / lo u8 planes; two s32 GEMMs, i64 combine.
// NHWC repack + zero halo + implicit im2col (K = (kh,kw,cin)).
// R14 was an infra failure (container died; kernel never ran) -> resubmit.
// Theory: register-fragment DOUBLE BUFFERING (CUTLASS-style) so MMA issue
// always overlaps LDSM latency, including across the chunk barrier.
// 2 CTAs/SM (128-reg budget), 16 warps. Detection lives in prep (g_flag).
// ============================================================

static constexpr int NB    = 8;
static constexpr int CIN   = 128;
static constexpr int COUT  = 256;
static constexpr int HW    = 56;
static constexpr int HW2   = HW * HW;           // 3136
static constexpr int NPIX  = NB * HW2;          // 25088
static constexpr int KDIM  = CIN * 9;           // 1152
static constexpr int SHIFT = 16;
static constexpr int PHW   = HW + 2;            // 58

static constexpr int CTA_M = 128;
static constexpr int CTA_N = 32;
static constexpr int KC    = 64;
static constexpr int NCHUNK = KDIM / KC;        // 18
static constexpr int M_TILES = NPIX / CTA_M;    // 196
static constexpr int N_TILES = COUT / CTA_N;    // 8
static constexpr int NTILE_TOT = M_TILES * N_TILES;  // 1568
static constexpr int THREADS = 256;             // 8 warps: 4(M) x 2(N), tile 32x16
static constexpr int GRIDP   = 296;             // 148 SMs x 2 CTAs

static constexpr int STAGES  = 4;
static constexpr int PITCH   = 80;
static constexpr int SM_TILE_A = 128 * PITCH;   // 10240
static constexpr int SM_TILE_B = 32 * PITCH;    // 2560
static constexpr int SM_STAGE  = SM_TILE_A + 2 * SM_TILE_B;  // 15360
static constexpr int SM_TOTAL  = STAGES * SM_STAGE;          // 61440

static constexpr int FLAG_I64 = 0, FLAG_I32 = 1, FLAG_F32 = 2, FLAG_F64 = 3;

// ---------------- scratch ----------------
__device__ __align__(128) int8_t g_Xt[(size_t)NB * PHW * PHW * CIN];  // 3.44MB
__device__ __align__(128) int8_t g_W[2 * (size_t)COUT * KDIM];        // hi|lo planes
__device__ int g_flag;

// ---------------- PTX helpers ----------------
__device__ __forceinline__ uint32_t smem_to_u32(const void* p) {
    uint32_t a;
    asm("{ .reg .u64 t; cvta.to.shared.u64 t, %1; cvt.u32.u64 %0, t; }" : "=r"(a) : "l"(p));
    return a;
}
__device__ __forceinline__ void cp16(uint32_t dst, const void* src) {
    asm volatile("cp.async.cg.shared.global [%0], [%1], 16;" :: "r"(dst), "l"(src));
}
#define CP_COMMIT() asm volatile("cp.async.commit_group;" ::: "memory")
#define CP_WAIT(n)  asm volatile("cp.async.wait_group %0;" :: "n"(n) : "memory")

__device__ __forceinline__ void ldsm_x4(uint32_t* r, uint32_t addr) {
    asm volatile("ldmatrix.sync.aligned.m8n8.x4.shared.b16 {%0,%1,%2,%3}, [%4];"
                 : "=r"(r[0]), "=r"(r[1]), "=r"(r[2]), "=r"(r[3]) : "r"(addr));
}
__device__ __forceinline__ void mma_s8s8(int* c, const uint32_t* a, const uint32_t* b) {
    asm volatile("mma.sync.aligned.m16n8k32.row.col.s32.s8.s8.s32 "
                 "{%0,%1,%2,%3}, {%4,%5,%6,%7}, {%8,%9}, {%0,%1,%2,%3};"
                 : "+r"(c[0]), "+r"(c[1]), "+r"(c[2]), "+r"(c[3])
                 : "r"(a[0]), "r"(a[1]), "r"(a[2]), "r"(a[3]), "r"(b[0]), "r"(b[1]));
}
__device__ __forceinline__ void mma_s8u8(int* c, const uint32_t* a, const uint32_t* b) {
    asm volatile("mma.sync.aligned.m16n8k32.row.col.s32.s8.u8.s32 "
                 "{%0,%1,%2,%3}, {%4,%5,%6,%7}, {%8,%9}, {%0,%1,%2,%3};"
                 : "+r"(c[0]), "+r"(c[1]), "+r"(c[2]), "+r"(c[3])
                 : "r"(a[0]), "r"(a[1]), "r"(a[2]), "r"(a[3]), "r"(b[0]), "r"(b[1]));
}

// ---------------- dtype detection (inside prep; block 0 publishes) ----------------
__device__ __forceinline__ int detect_flag_warp(const void* xraw, int lane) {
    const int* w = (const int*)xraw;
    int signext = 0, small = 0, lozero = 0;
#pragma unroll
    for (int j = 0; j < 4; j++) {
        int i = lane + j * 32;
        int lo = w[2 * i], hi = w[2 * i + 1];
        if (hi == (lo < 0 ? -1 : 0)) signext++;
        if (lo >= -256 && lo < 256 && hi >= -256 && hi < 256) small++;
        if (lo == 0) lozero++;
    }
#pragma unroll
    for (int off = 16; off > 0; off >>= 1) {
        signext += __shfl_down_sync(0xffffffffu, signext, off);
        small   += __shfl_down_sync(0xffffffffu, small,   off);
        lozero  += __shfl_down_sync(0xffffffffu, lozero,  off);
    }
    int f = FLAG_F32;
    if (signext >= 120)      f = FLAG_I64;
    else if (small >= 120)   f = FLAG_I32;
    else if (lozero >= 100)  f = FLAG_F64;
    return f;   // valid on lane 0
}

__device__ __forceinline__ long long load_val(const void* p, size_t idx, int flag) {
    if (flag == FLAG_I64) return ((const long long*)p)[idx];
    if (flag == FLAG_I32) return (long long)((const int*)p)[idx];
    if (flag == FLAG_F64) return __double2ll_rn(((const double*)p)[idx]);
    return (long long)__float2ll_rn(((const float*)p)[idx]);
}

// ---------------- merged prep: transpose (blocks 0..463) + weights (rest) ----------------
static constexpr int TR_BLOCKS = NB * PHW;                 // 464
static constexpr int PW_BLOCKS = (COUT * KDIM) / 256;      // 1152

__global__ void __launch_bounds__(256)
prep_kernel(const void* __restrict__ x, const void* __restrict__ wq) {
    __shared__ int s_flag;
    __shared__ int8_t s[CIN * (HW + 1)];
    int t = threadIdx.x;
    if (t < 32) {
        int f = detect_flag_warp(x, t);
        if (t == 0) {
            s_flag = f;
            if (blockIdx.x == 0) g_flag = f;   // publish for gemm
        }
    }
    __syncthreads();
    const int flag = s_flag;

    if (blockIdx.x >= TR_BLOCKS) {
        int idx = (blockIdx.x - TR_BLOCKS) * 256 + t;
        int co = idx / KDIM;
        int r  = idx - co * KDIM;
        int cin  = r / 9;
        int khkw = r - cin * 9;
        int kp = khkw * CIN + cin;
        long long w = load_val(wq, idx, flag);
        g_W[(size_t)co * KDIM + kp] = (int8_t)(w >> 8);
        g_W[(size_t)COUT * KDIM + (size_t)co * KDIM + kp] = (int8_t)(w & 255);
        return;
    }
    int b  = blockIdx.x;
    int n  = b / PHW;
    int ph = b - n * PHW;
    int8_t* dst = g_Xt + ((size_t)(n * PHW + ph) * PHW) * CIN;

    if (ph == 0 || ph == PHW - 1) {
        for (int i = t; i < PHW * CIN / 4; i += 256) ((int*)dst)[i] = 0;
        return;
    }
    int h = ph - 1;
    for (int i = t; i < CIN * HW; i += 256) {
        int c = i / HW, w = i - c * HW;
        long long v = load_val(x, ((size_t)(n * CIN + c) * HW + h) * HW + w, flag);
        s[c * (HW + 1) + w] = (int8_t)v;
    }
    __syncthreads();
    for (int i = t; i < PHW * (CIN / 4); i += 256) {
        int pw = i >> 5;
        int c0 = (i & 31) * 4;
        uint32_t word = 0;
        if (pw >= 1 && pw <= HW) {
            int w = pw - 1;
            uchar4 u;
            u.x = (uint8_t)s[(c0 + 0) * (HW + 1) + w];
            u.y = (uint8_t)s[(c0 + 1) * (HW + 1) + w];
            u.z = (uint8_t)s[(c0 + 2) * (HW + 1) + w];
            u.w = (uint8_t)s[(c0 + 3) * (HW + 1) + w];
            word = *(uint32_t*)&u;
        }
        ((uint32_t*)dst)[i] = word;
    }
}

// ---------------- persistent GEMM, register-fragment double buffering ----------------
__global__ void __launch_bounds__(THREADS, 2)
gemm_kernel(const void* __restrict__ bias, void* __restrict__ outv) {
    extern __shared__ char smem[];
    const uint32_t smb = smem_to_u32(smem);
    const int tid  = threadIdx.x;
    const int lane = tid & 31;
    const int wrp  = tid >> 5;
    const int wm   = wrp & 3;      // warp M (0..3), 32 rows
    const int wn   = wrp >> 2;     // warp N (0..1), 16 cols
    const int flag = g_flag;

    const int rowA0 = tid >> 2;           // 0..63
    const int rowA1 = rowA0 + 64;
    const int c16   = tid & 3;
    const int planeB = tid >> 7;          // 0..1
    const int rowB   = (tid >> 2) & 31;   // 0..31

    const uint32_t sA0 = smb + rowA0 * PITCH + c16 * 16;
    const uint32_t sA1 = smb + rowA1 * PITCH + c16 * 16;
    const uint32_t sBw = smb + SM_TILE_A + planeB * SM_TILE_B + rowB * PITCH + c16 * 16;

    // precomputed LDSM offsets (within a stage)
    const uint32_t offA0 = (uint32_t)((wm * 32 + (lane & 15)) * PITCH + (lane >> 4) * 16);
    const uint32_t offB  = (uint32_t)((wn * 16 + (lane & 7) + ((lane >> 4) << 3)) * PITCH
                                      + ((lane >> 3) & 1) * 16);

    for (int tile = blockIdx.x; tile < NTILE_TOT; tile += GRIDP) {
        const int mt = tile >> 3;
        const int nt = tile & 7;

        auto arow_ptr = [&](int r) -> const int8_t* {
            int p_ = mt * CTA_M + r;
            int n_ = p_ / HW2;
            int hw_ = p_ - n_ * HW2;
            int h_ = hw_ / HW;
            int w_ = hw_ - h_ * HW;
            return g_Xt + ((size_t)((n_ * PHW + h_ + 1) * PHW + (w_ + 1))) * CIN + c16 * 16;
        };
        const int8_t* Arow0 = arow_ptr(rowA0);
        const int8_t* Arow1 = arow_ptr(rowA1);
        const int8_t* Wb = g_W + (size_t)planeB * COUT * KDIM
                           + (size_t)(nt * CTA_N + rowB) * KDIM + c16 * 16;

        int acch[2][2][4];
        int accl[2][2][4];
#pragma unroll
        for (int mb = 0; mb < 2; mb++)
#pragma unroll
            for (int q = 0; q < 2; q++)
#pragma unroll
                for (int i = 0; i < 4; i++) { acch[mb][q][i] = 0; accl[mb][q][i] = 0; }

        auto load_chunk = [&](int kc, int buf) {
            int khkw = kc >> 1;
            int kh = khkw / 3;
            int kw = khkw - kh * 3;
            int off = ((kh - 1) * PHW + (kw - 1)) * CIN + (kc & 1) * KC;
            uint32_t sb = buf * SM_STAGE;
            cp16(sA0 + sb, Arow0 + off);
            cp16(sA1 + sb, Arow1 + off);
            cp16(sBw + sb, Wb + kc * KC);
        };

        // fragment double buffers
        uint32_t fa[2][2][4];    // [buf][mb][4]
        uint32_t fbh[2][4], fbl[2][4];

        auto ldsm_frags = [&](int fb, uint32_t smA, int ks) {
            uint32_t kof = (uint32_t)(ks * 32);   // ks*2 16B columns
#pragma unroll
            for (int mb = 0; mb < 2; mb++)
                ldsm_x4(fa[fb][mb], smA + offA0 + (uint32_t)(mb * 16 * PITCH) + kof);
            uint32_t smBh = smA + SM_TILE_A;
            ldsm_x4(fbh[fb], smBh + offB + kof);
            ldsm_x4(fbl[fb], smBh + SM_TILE_B + offB + kof);
        };
        auto mma_all = [&](int fb) {
#pragma unroll
            for (int mb = 0; mb < 2; mb++)
#pragma unroll
                for (int q = 0; q < 2; q++) {
                    mma_s8s8(acch[mb][q], fa[fb][mb], &fbh[fb][q * 2]);
                    mma_s8u8(accl[mb][q], fa[fb][mb], &fbl[fb][q * 2]);
                }
        };

        __syncthreads();   // previous tile's smem reads complete before refill

#pragma unroll
        for (int s = 0; s < STAGES - 1; s++) { load_chunk(s, s); CP_COMMIT(); }
        CP_WAIT(STAGES - 2);
        __syncthreads();
        ldsm_frags(0, smb, 0);   // chunk 0, ks 0

        for (int kc = 0; kc < NCHUNK; kc++) {
            const uint32_t smA = smb + (kc & (STAGES - 1)) * SM_STAGE;
            // ks1 fragments, then MMAs for ks0 (independent -> overlap)
            ldsm_frags(1, smA, 1);
            mma_all(0);
            // prefetch next chunk into the stage freed at kc-1
            {
                int nk = kc + STAGES - 1;
                if (nk < NCHUNK) load_chunk(nk, nk & (STAGES - 1));
                CP_COMMIT();
            }
            if (kc + 1 < NCHUNK) {
                CP_WAIT(STAGES - 2);
                __syncthreads();
                ldsm_frags(0, smb + ((kc + 1) & (STAGES - 1)) * SM_STAGE, 0);
            }
            // ks1 MMAs issue after the barrier, covering next-stage latency
            mma_all(1);
        }

        // ---- epilogue ----
        const int co_b = nt * CTA_N + wn * 16 + (lane & 3) * 2;
        long long bset[2][2];
#pragma unroll
        for (int q = 0; q < 2; q++) {
            bset[q][0] = load_val(bias, co_b + q * 8, flag);
            bset[q][1] = load_val(bias, co_b + q * 8 + 1, flag);
        }
#pragma unroll
        for (int mb = 0; mb < 2; mb++) {
#pragma unroll
            for (int q = 0; q < 2; q++) {
                int p0  = mt * CTA_M + wm * 32 + mb * 16 + (lane >> 2);
                int co0 = co_b + q * 8;
#pragma unroll
                for (int i = 0; i < 4; i++) {
                    int p  = p0 + ((i >= 2) ? 8 : 0);
                    int co = co0 + (i & 1);
                    long long v = (((long long)acch[mb][q][i] << 8)
                                   + (long long)accl[mb][q][i] + bset[q][i & 1]) >> SHIFT;
                    int n  = p / HW2;
                    int hw = p - n * HW2;
                    size_t oi = ((size_t)(n * COUT + co)) * HW2 + hw;
                    if (flag == FLAG_I64)      ((long long*)outv)[oi] = v;
                    else if (flag == FLAG_F64) ((double*)outv)[oi] = (double)v;
                    else                       ((float*)outv)[oi] = (float)v;
                }
            }
        }
    }
}

// ---------------- launch ----------------
extern "C" void kernel_launch(void* const* d_in, const int* in_sizes, int n_in,
                              void* d_out, int out_size) {
    const void* x = nullptr; const void* wq = nullptr; const void* bias = nullptr;
    for (int i = 0; i < n_in; i++) {
        if (in_sizes[i] == NB * CIN * HW2)      x    = d_in[i];
        else if (in_sizes[i] == COUT * KDIM)    wq   = d_in[i];
        else if (in_sizes[i] == COUT)           bias = d_in[i];
    }
    (void)out_size;

    prep_kernel<<<TR_BLOCKS + PW_BLOCKS, 256>>>(x, wq);

    cudaFuncSetAttribute(gemm_kernel, cudaFuncAttributeMaxDynamicSharedMemorySize, SM_TOTAL);
    gemm_kernel<<<GRIDP, THREADS, SM_TOTAL>>>(bias, d_out);
}

// round 16
// speedup vs baseline: 1.0947x; 1.0947x over previous
#include <cuda_runtime.h>
#include <cuda.h>
#include <cstdint>

// ============================================================
// QuantizedConv2d exact int conv via split-weight int8 mma.sync GEMM
//   x[8,128,56,56], w[256,128,3,3], bias[256], shift=16 (structural)
//   out[8,256,56,56] = (conv(x,w)+bias) >> 16
// w = (w>>8)*256 + (w&255): hi s8 / lo u8 planes; two s32 GEMMs, i64 combine.
// NHWC repack + zero halo + implicit im2col (K = (kh,kw,cin)).
// R15 post-mortem: register double-buffering raised issue% but cost occupancy
// (96 regs -> 2 CTA/SM) -> net loss. Five mainloop variants all plateau at the
// legacy-IMMA floor (~26.5us tensor-busy). Locking the best-known mainloop:
// R11's static persistent GEMM (444 CTAs, 3/SM, 80 regs, KC=64, 4-stage),
// detection ONLY in prep (publishes g_flag), GEMM reads the flag (one LDG).
// ============================================================

static constexpr int NB    = 8;
static constexpr int CIN   = 128;
static constexpr int COUT  = 256;
static constexpr int HW    = 56;
static constexpr int HW2   = HW * HW;           // 3136
static constexpr int NPIX  = NB * HW2;          // 25088
static constexpr int KDIM  = CIN * 9;           // 1152
static constexpr int SHIFT = 16;
static constexpr int PHW   = HW + 2;            // 58

static constexpr int CTA_M = 128;
static constexpr int CTA_N = 32;
static constexpr int KC    = 64;
static constexpr int NCHUNK = KDIM / KC;        // 18
static constexpr int M_TILES = NPIX / CTA_M;    // 196
static constexpr int N_TILES = COUT / CTA_N;    // 8
static constexpr int NTILE_TOT = M_TILES * N_TILES;  // 1568
static constexpr int THREADS = 256;             // 8 warps: 4(M) x 2(N), tile 32x16
static constexpr int GRIDP   = 444;             // 148 SMs x 3 CTAs

static constexpr int STAGES  = 4;
static constexpr int PITCH   = 80;
static constexpr int SM_TILE_A = 128 * PITCH;   // 10240
static constexpr int SM_TILE_B = 32 * PITCH;    // 2560
static constexpr int SM_STAGE  = SM_TILE_A + 2 * SM_TILE_B;  // 15360
static constexpr int SM_TOTAL  = STAGES * SM_STAGE;          // 61440

static constexpr int FLAG_I64 = 0, FLAG_I32 = 1, FLAG_F32 = 2, FLAG_F64 = 3;

// ---------------- scratch ----------------
__device__ __align__(128) int8_t g_Xt[(size_t)NB * PHW * PHW * CIN];  // 3.44MB
__device__ __align__(128) int8_t g_W[2 * (size_t)COUT * KDIM];        // hi|lo planes
__device__ int g_flag;

// ---------------- PTX helpers ----------------
__device__ __forceinline__ uint32_t smem_to_u32(const void* p) {
    uint32_t a;
    asm("{ .reg .u64 t; cvta.to.shared.u64 t, %1; cvt.u32.u64 %0, t; }" : "=r"(a) : "l"(p));
    return a;
}
__device__ __forceinline__ void cp16(uint32_t dst, const void* src) {
    asm volatile("cp.async.cg.shared.global [%0], [%1], 16;" :: "r"(dst), "l"(src));
}
#define CP_COMMIT() asm volatile("cp.async.commit_group;" ::: "memory")
#define CP_WAIT(n)  asm volatile("cp.async.wait_group %0;" :: "n"(n) : "memory")

__device__ __forceinline__ void ldsm_x4(uint32_t* r, uint32_t addr) {
    asm volatile("ldmatrix.sync.aligned.m8n8.x4.shared.b16 {%0,%1,%2,%3}, [%4];"
                 : "=r"(r[0]), "=r"(r[1]), "=r"(r[2]), "=r"(r[3]) : "r"(addr));
}
__device__ __forceinline__ void mma_s8s8(int* c, const uint32_t* a, const uint32_t* b) {
    asm volatile("mma.sync.aligned.m16n8k32.row.col.s32.s8.s8.s32 "
                 "{%0,%1,%2,%3}, {%4,%5,%6,%7}, {%8,%9}, {%0,%1,%2,%3};"
                 : "+r"(c[0]), "+r"(c[1]), "+r"(c[2]), "+r"(c[3])
                 : "r"(a[0]), "r"(a[1]), "r"(a[2]), "r"(a[3]), "r"(b[0]), "r"(b[1]));
}
__device__ __forceinline__ void mma_s8u8(int* c, const uint32_t* a, const uint32_t* b) {
    asm volatile("mma.sync.aligned.m16n8k32.row.col.s32.s8.u8.s32 "
                 "{%0,%1,%2,%3}, {%4,%5,%6,%7}, {%8,%9}, {%0,%1,%2,%3};"
                 : "+r"(c[0]), "+r"(c[1]), "+r"(c[2]), "+r"(c[3])
                 : "r"(a[0]), "r"(a[1]), "r"(a[2]), "r"(a[3]), "r"(b[0]), "r"(b[1]));
}

// ---------------- dtype detection (inside prep; block 0 publishes) ----------------
__device__ __forceinline__ int detect_flag_warp(const void* xraw, int lane) {
    const int* w = (const int*)xraw;
    int signext = 0, small = 0, lozero = 0;
#pragma unroll
    for (int j = 0; j < 4; j++) {
        int i = lane + j * 32;
        int lo = w[2 * i], hi = w[2 * i + 1];
        if (hi == (lo < 0 ? -1 : 0)) signext++;
        if (lo >= -256 && lo < 256 && hi >= -256 && hi < 256) small++;
        if (lo == 0) lozero++;
    }
#pragma unroll
    for (int off = 16; off > 0; off >>= 1) {
        signext += __shfl_down_sync(0xffffffffu, signext, off);
        small   += __shfl_down_sync(0xffffffffu, small,   off);
        lozero  += __shfl_down_sync(0xffffffffu, lozero,  off);
    }
    int f = FLAG_F32;
    if (signext >= 120)      f = FLAG_I64;
    else if (small >= 120)   f = FLAG_I32;
    else if (lozero >= 100)  f = FLAG_F64;
    return f;   // valid on lane 0
}

__device__ __forceinline__ long long load_val(const void* p, size_t idx, int flag) {
    if (flag == FLAG_I64) return ((const long long*)p)[idx];
    if (flag == FLAG_I32) return (long long)((const int*)p)[idx];
    if (flag == FLAG_F64) return __double2ll_rn(((const double*)p)[idx]);
    return (long long)__float2ll_rn(((const float*)p)[idx]);
}

// ---------------- merged prep: transpose (blocks 0..463) + weights (rest) ----------------
static constexpr int TR_BLOCKS = NB * PHW;                 // 464
static constexpr int PW_BLOCKS = (COUT * KDIM) / 256;      // 1152

__global__ void __launch_bounds__(256)
prep_kernel(const void* __restrict__ x, const void* __restrict__ wq) {
    __shared__ int s_flag;
    __shared__ int8_t s[CIN * (HW + 1)];
    int t = threadIdx.x;
    if (t < 32) {
        int f = detect_flag_warp(x, t);
        if (t == 0) {
            s_flag = f;
            if (blockIdx.x == 0) g_flag = f;   // publish for gemm
        }
    }
    __syncthreads();
    const int flag = s_flag;

    if (blockIdx.x >= TR_BLOCKS) {
        int idx = (blockIdx.x - TR_BLOCKS) * 256 + t;
        int co = idx / KDIM;
        int r  = idx - co * KDIM;
        int cin  = r / 9;
        int khkw = r - cin * 9;
        int kp = khkw * CIN + cin;
        long long w = load_val(wq, idx, flag);
        g_W[(size_t)co * KDIM + kp] = (int8_t)(w >> 8);
        g_W[(size_t)COUT * KDIM + (size_t)co * KDIM + kp] = (int8_t)(w & 255);
        return;
    }
    int b  = blockIdx.x;
    int n  = b / PHW;
    int ph = b - n * PHW;
    int8_t* dst = g_Xt + ((size_t)(n * PHW + ph) * PHW) * CIN;

    if (ph == 0 || ph == PHW - 1) {
        for (int i = t; i < PHW * CIN / 4; i += 256) ((int*)dst)[i] = 0;
        return;
    }
    int h = ph - 1;
    for (int i = t; i < CIN * HW; i += 256) {
        int c = i / HW, w = i - c * HW;
        long long v = load_val(x, ((size_t)(n * CIN + c) * HW + h) * HW + w, flag);
        s[c * (HW + 1) + w] = (int8_t)v;
    }
    __syncthreads();
    for (int i = t; i < PHW * (CIN / 4); i += 256) {
        int pw = i >> 5;
        int c0 = (i & 31) * 4;
        uint32_t word = 0;
        if (pw >= 1 && pw <= HW) {
            int w = pw - 1;
            uchar4 u;
            u.x = (uint8_t)s[(c0 + 0) * (HW + 1) + w];
            u.y = (uint8_t)s[(c0 + 1) * (HW + 1) + w];
            u.z = (uint8_t)s[(c0 + 2) * (HW + 1) + w];
            u.w = (uint8_t)s[(c0 + 3) * (HW + 1) + w];
            word = *(uint32_t*)&u;
        }
        ((uint32_t*)dst)[i] = word;
    }
}

// ---------------- persistent implicit-im2col GEMM (static tiles) ----------------
__global__ void __launch_bounds__(THREADS, 3)
gemm_kernel(const void* __restrict__ bias, void* __restrict__ outv) {
    extern __shared__ char smem[];
    const uint32_t smb = smem_to_u32(smem);
    const int tid  = threadIdx.x;
    const int lane = tid & 31;
    const int wrp  = tid >> 5;
    const int wm   = wrp & 3;      // warp M (0..3), 32 rows
    const int wn   = wrp >> 2;     // warp N (0..1), 16 cols
    const int flag = g_flag;       // published by prep (prior launch)

    const int rowA0 = tid >> 2;           // 0..63
    const int rowA1 = rowA0 + 64;
    const int c16   = tid & 3;
    const int planeB = tid >> 7;          // 0..1
    const int rowB   = (tid >> 2) & 31;   // 0..31

    const uint32_t sA0 = smb + rowA0 * PITCH + c16 * 16;
    const uint32_t sA1 = smb + rowA1 * PITCH + c16 * 16;
    const uint32_t sBw = smb + SM_TILE_A + planeB * SM_TILE_B + rowB * PITCH + c16 * 16;

    for (int tile = blockIdx.x; tile < NTILE_TOT; tile += GRIDP) {
        const int mt = tile >> 3;
        const int nt = tile & 7;

        auto arow_ptr = [&](int r) -> const int8_t* {
            int p_ = mt * CTA_M + r;
            int n_ = p_ / HW2;
            int hw_ = p_ - n_ * HW2;
            int h_ = hw_ / HW;
            int w_ = hw_ - h_ * HW;
            return g_Xt + ((size_t)((n_ * PHW + h_ + 1) * PHW + (w_ + 1))) * CIN + c16 * 16;
        };
        const int8_t* Arow0 = arow_ptr(rowA0);
        const int8_t* Arow1 = arow_ptr(rowA1);
        const int8_t* Wb = g_W + (size_t)planeB * COUT * KDIM
                           + (size_t)(nt * CTA_N + rowB) * KDIM + c16 * 16;

        int acch[2][2][4];
        int accl[2][2][4];
#pragma unroll
        for (int mb = 0; mb < 2; mb++)
#pragma unroll
            for (int q = 0; q < 2; q++)
#pragma unroll
                for (int i = 0; i < 4; i++) { acch[mb][q][i] = 0; accl[mb][q][i] = 0; }

        auto load_chunk = [&](int kc, int buf) {
            int khkw = kc >> 1;
            int kh = khkw / 3;
            int kw = khkw - kh * 3;
            int off = ((kh - 1) * PHW + (kw - 1)) * CIN + (kc & 1) * KC;
            uint32_t sb = buf * SM_STAGE;
            cp16(sA0 + sb, Arow0 + off);
            cp16(sA1 + sb, Arow1 + off);
            cp16(sBw + sb, Wb + kc * KC);
        };

        __syncthreads();   // previous tile's smem reads complete before refill

#pragma unroll
        for (int s = 0; s < STAGES - 1; s++) { load_chunk(s, s); CP_COMMIT(); }

        for (int kc = 0; kc < NCHUNK; kc++) {
            CP_WAIT(STAGES - 2);
            __syncthreads();
            {
                int nk = kc + STAGES - 1;
                if (nk < NCHUNK) load_chunk(nk, nk & (STAGES - 1));
                CP_COMMIT();
            }

            const uint32_t smA  = smb + (kc & (STAGES - 1)) * SM_STAGE;
            const uint32_t smBh = smA + SM_TILE_A;
            const uint32_t smBl = smBh + SM_TILE_B;

#pragma unroll
            for (int ks = 0; ks < 2; ks++) {
                uint32_t a[2][4];
#pragma unroll
                for (int mb = 0; mb < 2; mb++) {
                    uint32_t addr = smA + (uint32_t)((wm * 32 + mb * 16 + (lane & 15)) * PITCH
                                                     + (ks * 2 + (lane >> 4)) * 16);
                    ldsm_x4(a[mb], addr);
                }
                uint32_t bh[4], bl[4];
                {
                    uint32_t boff = (uint32_t)((wn * 16 + (lane & 7) + ((lane >> 4) << 3)) * PITCH
                                               + (ks * 2 + ((lane >> 3) & 1)) * 16);
                    ldsm_x4(bh, smBh + boff);
                    ldsm_x4(bl, smBl + boff);
                }
#pragma unroll
                for (int mb = 0; mb < 2; mb++)
#pragma unroll
                    for (int q = 0; q < 2; q++) {
                        mma_s8s8(acch[mb][q], a[mb], &bh[q * 2]);
                        mma_s8u8(accl[mb][q], a[mb], &bl[q * 2]);
                    }
            }
        }

        // ---- epilogue ----
        const int co_b = nt * CTA_N + wn * 16 + (lane & 3) * 2;
        long long bset[2][2];
#pragma unroll
        for (int q = 0; q < 2; q++) {
            bset[q][0] = load_val(bias, co_b + q * 8, flag);
            bset[q][1] = load_val(bias, co_b + q * 8 + 1, flag);
        }
#pragma unroll
        for (int mb = 0; mb < 2; mb++) {
#pragma unroll
            for (int q = 0; q < 2; q++) {
                int p0  = mt * CTA_M + wm * 32 + mb * 16 + (lane >> 2);
                int co0 = co_b + q * 8;
#pragma unroll
                for (int i = 0; i < 4; i++) {
                    int p  = p0 + ((i >= 2) ? 8 : 0);
                    int co = co0 + (i & 1);
                    long long v = (((long long)acch[mb][q][i] << 8)
                                   + (long long)accl[mb][q][i] + bset[q][i & 1]) >> SHIFT;
                    int n  = p / HW2;
                    int hw = p - n * HW2;
                    size_t oi = ((size_t)(n * COUT + co)) * HW2 + hw;
                    if (flag == FLAG_I64)      ((long long*)outv)[oi] = v;
                    else if (flag == FLAG_F64) ((double*)outv)[oi] = (double)v;
                    else                       ((float*)outv)[oi] = (float)v;
                }
            }
        }
    }
}

// ---------------- launch ----------------
extern "C" void kernel_launch(void* const* d_in, const int* in_sizes, int n_in,
                              void* d_out, int out_size) {
    const void* x = nullptr; const void* wq = nullptr; const void* bias = nullptr;
    for (int i = 0; i < n_in; i++) {
        if (in_sizes[i] == NB * CIN * HW2)      x    = d_in[i];
        else if (in_sizes[i] == COUT * KDIM)    wq   = d_in[i];
        else if (in_sizes[i] == COUT)           bias = d_in[i];
    }
    (void)out_size;

    prep_kernel<<<TR_BLOCKS + PW_BLOCKS, 256>>>(x, wq);

    cudaFuncSetAttribute(gemm_kernel, cudaFuncAttributeMaxDynamicSharedMemorySize, SM_TOTAL);
    gemm_kernel<<<GRIDP, THREADS, SM_TOTAL>>>(bias, d_out);
}